// round 15
// baseline (speedup 1.0000x reference)
#include <cuda_runtime.h>
#include <math.h>
#include <stdint.h>

#define B_   2
#define L_   2048
#define DM   1024
#define DI   2048
#define DS   16
#define TOK  (B_*L_)
#define KCH  16            // split-K chunks for BC gemm
#define KCW  (DI / KCH)    // 128
#define CH   32            // scan time-chunk

#define GST      3                      // gemm pipeline stages
#define GSM_PER  (128 * 20)             // floats per operand-stage
#define GSM_BYTES (GST * GSM_PER * 2 * 4)   // 61440 B dynamic smem

// ---------------- scratch (device globals; no allocs allowed) ----------------
__device__ float g_xn[TOK * DM];
__device__ float g_xz[TOK * 2 * DI];
__device__ float g_xconv[TOK * DI];
__device__ float g_dt[TOK * DI];
__device__ float g_BC[TOK * 2 * DS];
__device__ float g_BCp[KCH][TOK * 2 * DS];   // split-K partials (8MB)
__device__ float g_y[TOK * DI];
__device__ float g_A[DI * DS];
__device__ float g_Win[2 * DI * DM];         // pre-rounded weights (tf32-rna)
__device__ float g_Wdt[DI * DI];
__device__ float g_Wout[DM * DI];

// ---------------- helpers ----------------
__inline__ __device__ float warpsum(float v) {
    #pragma unroll
    for (int m = 16; m; m >>= 1) v += __shfl_xor_sync(0xffffffffu, v, m);
    return v;
}

#define RND_TF32(f) (__float_as_uint(f) + 0x1000u)   // round-to-nearest; mma ignores low 13 bits
#define RNDF(f) __uint_as_float(RND_TF32(f))

__device__ __forceinline__ void mma_tf32(float* c, const uint32_t* a, const uint32_t* b) {
    asm volatile(
        "mma.sync.aligned.m16n8k8.row.col.f32.tf32.tf32.f32 "
        "{%0,%1,%2,%3}, {%4,%5,%6,%7}, {%8,%9}, {%0,%1,%2,%3};"
        : "+f"(c[0]), "+f"(c[1]), "+f"(c[2]), "+f"(c[3])
        : "r"(a[0]), "r"(a[1]), "r"(a[2]), "r"(a[3]), "r"(b[0]), "r"(b[1]));
}

// ---------------- tf32 round-copy of ALL weights in one launch ----------------
__global__ void rnd_all(const float* __restrict__ w_in, const float* __restrict__ w_dt,
                        const float* __restrict__ w_out) {
    const int n0 = 2 * DI * DM / 4;
    const int n1 = DI * DI / 4;
    const int n2 = DM * DI / 4;
    int i = blockIdx.x * blockDim.x + threadIdx.x;
    const float4* src; uint4* dst; int j;
    if (i < n0)               { src = (const float4*)w_in;  dst = (uint4*)g_Win;  j = i; }
    else if (i < n0 + n1)     { src = (const float4*)w_dt;  dst = (uint4*)g_Wdt;  j = i - n0; }
    else if (i < n0 + n1 + n2){ src = (const float4*)w_out; dst = (uint4*)g_Wout; j = i - n0 - n1; }
    else return;
    float4 f = src[j];
    dst[j] = make_uint4(RND_TF32(f.x), RND_TF32(f.y), RND_TF32(f.z), RND_TF32(f.w));
}

// ======================================================================
//  mma.sync TF32 GEMM: C = A[M,K] @ B[N,K]^T  (A,B pre-rounded to tf32)
//  CTA 128x128, BK=16, 8 warps in 2x4, warp tile 64x32 (<=128 regs ->
//  16 warps/SM).  3-stage cp.async pipeline (prefetch distance 2).
//  EPI: 0 none, 1 softplus(v+aux[col]), 2 v+aux[idx]
// ======================================================================
template<int EPI>
__global__ void __launch_bounds__(256, 2)
gemm_mma_kernel(const float* __restrict__ A, const float* __restrict__ Bw,
                float* __restrict__ C, int M, int N, int K,
                const float* __restrict__ aux)
{
    extern __shared__ __align__(16) float sm[];
    float* Asm = sm;                       // [GST][128][20]
    float* Bsm = sm + GST * GSM_PER;

    const int tid  = threadIdx.x;
    const int lane = tid & 31;
    const int warp = tid >> 5;
    const int g    = lane >> 2;
    const int tig  = lane & 3;
    const int wm   = warp >> 2;          // 0..1
    const int wn   = warp & 3;           // 0..3
    const int bm0  = blockIdx.y * 128;
    const int bn0  = blockIdx.x * 128;

    float acc[4][4][4];
    #pragma unroll
    for (int i = 0; i < 4; i++)
        #pragma unroll
        for (int j = 0; j < 4; j++)
            #pragma unroll
            for (int q = 0; q < 4; q++) acc[i][j][q] = 0.f;

    const int r0 = tid >> 2;   // 0..63 (+64)
    const int kq = tid & 3;    // k-quad

    const uint32_t aSm = (uint32_t)__cvta_generic_to_shared(Asm)
                       + (uint32_t)(r0 * 80 + kq * 16);
    const uint32_t bSm = (uint32_t)__cvta_generic_to_shared(Bsm)
                       + (uint32_t)(r0 * 80 + kq * 16);
    const uint32_t STB = GSM_PER * 4;    // 10240 B per stage

#define CPA_T(stg, k0) do { \
    const uint32_t bo = (uint32_t)(stg) * STB; \
    _Pragma("unroll") \
    for (int e = 0; e < 2; e++) { \
        asm volatile("cp.async.ca.shared.global [%0], [%1], 16;" :: \
            "r"(aSm + bo + (uint32_t)(e * 5120)), \
            "l"(A + (size_t)(bm0 + r0 + 64*e) * K + (k0) + 4*kq)); \
        asm volatile("cp.async.ca.shared.global [%0], [%1], 16;" :: \
            "r"(bSm + bo + (uint32_t)(e * 5120)), \
            "l"(Bw + (size_t)(bn0 + r0 + 64*e) * K + (k0) + 4*kq)); \
    } \
    asm volatile("cp.async.commit_group;"); \
} while (0)

    const int n_iter = K >> 4;
    CPA_T(0, 0);
    CPA_T(1, 16);
    asm volatile("cp.async.wait_group 1;");   // stage 0 ready
    __syncthreads();

    int cur = 0, pf = 2;
    for (int it = 0; it < n_iter; it++) {
        const bool more = (it + 2 < n_iter);
        if (more) CPA_T(pf, (it + 2) << 4);

        const float* Ab = Asm + cur * GSM_PER;
        const float* Bb = Bsm + cur * GSM_PER;
        #pragma unroll
        for (int ks = 0; ks < 2; ks++) {
            uint32_t af[4][4], bf[4][2];
            const int k0 = ks * 8 + tig;
            const int k1 = k0 + 4;
            #pragma unroll
            for (int i = 0; i < 4; i++) {
                const int row = wm * 64 + i * 16 + g;
                af[i][0] = __float_as_uint(Ab[row * 20 + k0]);
                af[i][1] = __float_as_uint(Ab[(row + 8) * 20 + k0]);
                af[i][2] = __float_as_uint(Ab[row * 20 + k1]);
                af[i][3] = __float_as_uint(Ab[(row + 8) * 20 + k1]);
            }
            #pragma unroll
            for (int j = 0; j < 4; j++) {
                const int col = wn * 32 + j * 8 + g;
                bf[j][0] = __float_as_uint(Bb[col * 20 + k0]);
                bf[j][1] = __float_as_uint(Bb[col * 20 + k1]);
            }
            #pragma unroll
            for (int i = 0; i < 4; i++)
                #pragma unroll
                for (int j = 0; j < 4; j++)
                    mma_tf32(acc[i][j], af[i], bf[j]);
        }
        if (more) asm volatile("cp.async.wait_group 1;");
        else      asm volatile("cp.async.wait_group 0;");
        __syncthreads();
        cur = (cur + 1 == GST) ? 0 : cur + 1;
        pf  = (pf  + 1 == GST) ? 0 : pf  + 1;
    }

    // ---- epilogue: direct STG (float2 pairs) ----
    #pragma unroll
    for (int i = 0; i < 4; i++) {
        const int row = bm0 + wm * 64 + i * 16 + g;
        #pragma unroll
        for (int j = 0; j < 4; j++) {
            const int col = bn0 + wn * 32 + j * 8 + 2 * tig;
            #pragma unroll
            for (int half = 0; half < 2; half++) {
                const int r = row + half * 8;
                float v0 = acc[i][j][half * 2 + 0];
                float v1 = acc[i][j][half * 2 + 1];
                size_t idx = (size_t)r * N + col;
                if (EPI == 1) {
                    v0 += aux[col];
                    v1 += aux[col + 1];
                    v0 = (v0 > 20.f) ? v0 : log1pf(__expf(v0));
                    v1 = (v1 > 20.f) ? v1 : log1pf(__expf(v1));
                } else if (EPI == 2) {
                    v0 += aux[idx];
                    v1 += aux[idx + 1];
                }
                *(float2*)(C + idx) = make_float2(v0, v1);
            }
        }
    }
#undef CPA_T
}

// ---------------- layernorm (writes tf32-rounded output) ----------------
__global__ void ln_kernel(const float* __restrict__ x, const float* __restrict__ w,
                          const float* __restrict__ b, float* __restrict__ out) {
    int t = blockIdx.x;
    int tid = threadIdx.x;
    const float* xr = x + (size_t)t * DM;
    float s = 0.f, sq = 0.f;
    for (int i = tid; i < DM; i += 256) { float v = xr[i]; s += v; sq += v * v; }
    s = warpsum(s); sq = warpsum(sq);
    __shared__ float sh0[8], sh1[8];
    int wi = tid >> 5, l = tid & 31;
    if (l == 0) { sh0[wi] = s; sh1[wi] = sq; }
    __syncthreads();
    if (wi == 0) {
        s  = (l < 8) ? sh0[l] : 0.f;
        sq = (l < 8) ? sh1[l] : 0.f;
        s = warpsum(s); sq = warpsum(sq);
        if (l == 0) { sh0[0] = s; sh1[0] = sq; }
    }
    __syncthreads();
    float mu  = sh0[0] * (1.f / DM);
    float var = sh1[0] * (1.f / DM) - mu * mu;
    float r = rsqrtf(var + 1e-5f);
    for (int i = tid; i < DM; i += 256)
        out[(size_t)t * DM + i] = RNDF((xr[i] - mu) * r * w[i] + b[i]);
}

// ---------------- A = -exp(A_log) ----------------
__global__ void prep_A(const float* __restrict__ Al, float* __restrict__ A) {
    int i = blockIdx.x * blockDim.x + threadIdx.x;
    if (i < DI * DS) A[i] = -expf(Al[i]);
}

// ---------------- BC split-K partial: 32x32 tile over K-chunk of 128 ----------------
__global__ void __launch_bounds__(256) bc_partial_kernel(
    const float* __restrict__ A, const float* __restrict__ Bp, const float* __restrict__ Bp2)
{
    constexpr int BM = 32, BN = 32, BK = 16, TM = 2, TN = 2;
    constexpr int PAD = 4;
    __shared__ float As[BK][BM + PAD];
    __shared__ float Bs[BK][BN + PAD];
    int tid = threadIdx.x;
    int kc  = blockIdx.x;                // 0..15
    int bm0 = blockIdx.y * BM;
    int kbeg = kc * KCW;
    constexpr int TX = BN / TN;
    int tx = tid % TX;
    int ty = tid / TX;

    float acc[TM][TN] = {};
    constexpr int AF4 = BM * BK / 4;
    constexpr int BF4 = BN * BK / 4;
    constexpr int KQ  = BK / 4;

    for (int k0 = kbeg; k0 < kbeg + KCW; k0 += BK) {
        #pragma unroll
        for (int q = tid; q < AF4; q += 256) {
            int row = q / KQ, c = q % KQ;
            float4 f = *(const float4*)(A + (size_t)(bm0 + row) * DI + k0 + 4 * c);
            As[4*c+0][row] = f.x; As[4*c+1][row] = f.y;
            As[4*c+2][row] = f.z; As[4*c+3][row] = f.w;
        }
        #pragma unroll
        for (int q = tid; q < BF4; q += 256) {
            int row = q / KQ, c = q % KQ;
            const float* src = (row < 16) ? (Bp + (size_t)row * DI) : (Bp2 + (size_t)(row - 16) * DI);
            float4 f = *(const float4*)(src + k0 + 4 * c);
            Bs[4*c+0][row] = f.x; Bs[4*c+1][row] = f.y;
            Bs[4*c+2][row] = f.z; Bs[4*c+3][row] = f.w;
        }
        __syncthreads();
        #pragma unroll
        for (int k = 0; k < BK; k++) {
            float a[TM], b[TN];
            #pragma unroll
            for (int i = 0; i < TM; i++) a[i] = As[k][ty * TM + i];
            #pragma unroll
            for (int j = 0; j < TN; j++) b[j] = Bs[k][tx * TN + j];
            #pragma unroll
            for (int i = 0; i < TM; i++)
                #pragma unroll
                for (int j = 0; j < TN; j++)
                    acc[i][j] = fmaf(a[i], b[j], acc[i][j]);
        }
        __syncthreads();
    }
    #pragma unroll
    for (int i = 0; i < TM; i++)
        #pragma unroll
        for (int j = 0; j < TN; j++)
            g_BCp[kc][(size_t)(bm0 + ty * TM + i) * 32 + tx * TN + j] = acc[i][j];
}

__global__ void bc_reduce_kernel() {
    int idx = blockIdx.x * blockDim.x + threadIdx.x;
    if (idx >= TOK * 32) return;
    float s = 0.f;
    #pragma unroll
    for (int kc = 0; kc < KCH; kc++) s += g_BCp[kc][idx];
    g_BC[idx] = s;
}

// ---------------- causal depthwise conv (K=4) + SiLU (tf32-rounded out) ----------------
__global__ void conv_silu_kernel(const float* __restrict__ cw, const float* __restrict__ cb) {
    int idx = blockIdx.x * blockDim.x + threadIdx.x;
    if (idx >= TOK * DI) return;
    int token = idx / DI;
    int c = idx - token * DI;
    int b = token / L_;
    int t = token - b * L_;
    float sum = cb[c];
    #pragma unroll
    for (int k = 0; k < 4; k++) {
        int tt = t - 3 + k;
        if (tt >= 0)
            sum = fmaf(g_xz[((size_t)(b * L_ + tt)) * (2 * DI) + c], cw[c * 4 + k], sum);
    }
    float s = sum / (1.f + __expf(-sum));
    g_xconv[idx] = RNDF(s);
}

// ======================================================================
//  selective scan v2 (R12 winner): 8 lanes/channel, 2 states/lane,
//  3-shfl reduce; writes tf32-rounded y for the out-GEMM.
// ======================================================================
__global__ void __launch_bounds__(256) scan_kernel(const float* __restrict__ Dv) {
    __shared__ float s_dt[2][CH][32];
    __shared__ float s_xc[2][CH][32];
    __shared__ float s_z [2][CH][32];
    __shared__ float s_bc[2][CH][32];
    __shared__ float s_y [CH][32];

    const int tid  = threadIdx.x;
    const int warp = tid >> 5;           // 0..7
    const int lane = tid & 31;
    const int b    = blockIdx.x >> 6;    // 64 d-blocks per batch
    const int dblk = (blockIdx.x & 63) * 32;
    const int sub  = lane & 7;           // state base index
    const int dgrp = lane >> 3;          // 0..3
    const int dl   = 4 * warp + dgrp;    // local channel 0..31
    const int d    = dblk + dl;

    const float a0 = g_A[d * DS + sub];
    const float a1 = g_A[d * DS + sub + 8];
    const float Dd = Dv[d];
    const size_t tok0 = (size_t)b * L_;

    float r_dt[4], r_xc[4], r_z[4], r_bc[4];

#define SCAN_LDG(t0) do { \
    _Pragma("unroll") \
    for (int e = 0; e < 4; e++) { \
        size_t tok = tok0 + (t0) + warp + 8 * e; \
        r_dt[e] = g_dt   [tok * DI + dblk + lane]; \
        r_xc[e] = g_xconv[tok * DI + dblk + lane]; \
        r_z [e] = g_xz   [tok * 2 * DI + DI + dblk + lane]; \
        r_bc[e] = g_BC   [tok * 32 + lane]; \
    } } while (0)

#define SCAN_STS(buf) do { \
    _Pragma("unroll") \
    for (int e = 0; e < 4; e++) { \
        int i = warp + 8 * e; \
        s_dt[buf][i][lane] = r_dt[e]; \
        s_xc[buf][i][lane] = r_xc[e]; \
        s_z [buf][i][lane] = r_z [e]; \
        s_bc[buf][i][lane] = r_bc[e]; \
    } } while (0)

    SCAN_LDG(0);
    SCAN_STS(0);
    __syncthreads();

    float h0 = 0.f, h1 = 0.f;
    const int n_chunks = L_ / CH;     // 64

    for (int c = 0; c < n_chunks; c++) {
        if (c + 1 < n_chunks) SCAN_LDG((c + 1) * CH);
        const int cur = c & 1;

        #pragma unroll
        for (int i = 0; i < CH; i++) {
            float dtv = s_dt[cur][i][dl];
            float xcv = s_xc[cur][i][dl];
            float B0  = s_bc[cur][i][sub];
            float B8  = s_bc[cur][i][sub + 8];
            float C0  = s_bc[cur][i][16 + sub];
            float C8  = s_bc[cur][i][24 + sub];
            float e0 = __expf(a0 * dtv);
            float e1 = __expf(a1 * dtv);
            float w  = xcv * dtv;
            h0 = fmaf(h0, e0, w * B0);
            h1 = fmaf(h1, e1, w * B8);
            float p = fmaf(h1, C8, h0 * C0);
            p += __shfl_xor_sync(0xffffffffu, p, 1);
            p += __shfl_xor_sync(0xffffffffu, p, 2);
            p += __shfl_xor_sync(0xffffffffu, p, 4);
            if (sub == 0) {
                float zv = s_z[cur][i][dl];
                float sig = zv / (1.f + __expf(-zv));
                s_y[i][dl] = (p + xcv * Dd) * sig;
            }
        }
        __syncthreads();   // scan reads + s_y writes done

        #pragma unroll
        for (int e = 0; e < 4; e++) {
            int i = warp + 8 * e;
            g_y[(tok0 + c * CH + i) * DI + dblk + lane] = RNDF(s_y[i][lane]);
        }
        if (c + 1 < n_chunks) SCAN_STS((c + 1) & 1);
        __syncthreads();   // next buffer ready; s_y drained
    }
#undef SCAN_LDG
#undef SCAN_STS
}

// ---------------- launch ----------------
extern "C" void kernel_launch(void* const* d_in, const int* in_sizes, int n_in,
                              void* d_out, int out_size) {
    const float* x      = (const float*)d_in[0];
    const float* norm_w = (const float*)d_in[1];
    const float* norm_b = (const float*)d_in[2];
    const float* W_in   = (const float*)d_in[3];
    const float* conv_w = (const float*)d_in[4];
    const float* conv_b = (const float*)d_in[5];
    const float* W_dt   = (const float*)d_in[6];
    const float* b_dt   = (const float*)d_in[7];
    const float* W_B    = (const float*)d_in[8];
    const float* W_C    = (const float*)d_in[9];
    const float* Dv     = (const float*)d_in[10];
    const float* A_log  = (const float*)d_in[11];
    const float* W_out  = (const float*)d_in[12];
    float* out = (float*)d_out;

    float *p_xn, *p_xz, *p_xc, *p_dt, *p_y, *p_A, *p_Win, *p_Wdt, *p_Wout;
    cudaGetSymbolAddress((void**)&p_xn, g_xn);
    cudaGetSymbolAddress((void**)&p_xz, g_xz);
    cudaGetSymbolAddress((void**)&p_xc, g_xconv);
    cudaGetSymbolAddress((void**)&p_dt, g_dt);
    cudaGetSymbolAddress((void**)&p_y,  g_y);
    cudaGetSymbolAddress((void**)&p_A,  g_A);
    cudaGetSymbolAddress((void**)&p_Win,  g_Win);
    cudaGetSymbolAddress((void**)&p_Wdt,  g_Wdt);
    cudaGetSymbolAddress((void**)&p_Wout, g_Wout);

    cudaFuncSetAttribute(gemm_mma_kernel<0>, cudaFuncAttributeMaxDynamicSharedMemorySize, GSM_BYTES);
    cudaFuncSetAttribute(gemm_mma_kernel<1>, cudaFuncAttributeMaxDynamicSharedMemorySize, GSM_BYTES);
    cudaFuncSetAttribute(gemm_mma_kernel<2>, cudaFuncAttributeMaxDynamicSharedMemorySize, GSM_BYTES);

    // 0. weights -> tf32-rounded copies (single launch)
    {
        int n4 = (2 * DI * DM + DI * DI + DM * DI) / 4;
        rnd_all<<<(n4 + 255) / 256, 256>>>(W_in, W_dt, W_out);
    }

    // 1. layernorm (rounded out)
    ln_kernel<<<TOK, 256>>>(x, norm_w, norm_b, p_xn);

    // 2. A = -exp(A_log)  (keeps in-proj GEMM at launch idx 3 for ncu)
    prep_A<<<(DI * DS + 255) / 256, 256>>>(A_log, p_A);

    // 3. in-proj: xz = xn @ W_in^T    [4096 x 4096 x 1024]
    {
        dim3 grid((2 * DI) / 128, TOK / 128);
        gemm_mma_kernel<0><<<grid, 256, GSM_BYTES>>>(p_xn, p_Win, p_xz, TOK, 2 * DI, DM, nullptr);
    }

    // 4. conv + silu (rounded out)
    conv_silu_kernel<<<(TOK * DI) / 256, 256>>>(conv_w, conv_b);

    // 5. dt = softplus(x_conv @ W_dt^T + b_dt)   [4096 x 2048 x 2048]
    {
        dim3 grid(DI / 128, TOK / 128);
        gemm_mma_kernel<1><<<grid, 256, GSM_BYTES>>>(p_xc, p_Wdt, p_dt, TOK, DI, DI, b_dt);
    }

    // 6. [B|C] split-K partials + reduce
    {
        dim3 grid(KCH, TOK / 32);
        bc_partial_kernel<<<grid, 256>>>(p_xc, W_B, W_C);
        bc_reduce_kernel<<<(TOK * 32 + 255) / 256, 256>>>();
    }

    // 7. selective scan + gating (rounded y out)
    scan_kernel<<<B_ * (DI / 32), 256>>>(Dv);

    // 8. out = residual + y @ W_out^T   [4096 x 1024 x 2048]
    {
        dim3 grid(DM / 128, TOK / 128);
        gemm_mma_kernel<2><<<grid, 256, GSM_BYTES>>>(p_y, p_Wout, out, TOK, DM, DI, x);
    }
}

// round 16
// speedup vs baseline: 1.1593x; 1.1593x over previous
#include <cuda_runtime.h>
#include <math.h>
#include <stdint.h>

#define B_   2
#define L_   2048
#define DM   1024
#define DI   2048
#define DS   16
#define TOK  (B_*L_)
#define KCH  16            // split-K chunks for BC gemm
#define KCW  (DI / KCH)    // 128
#define CH   32            // scan time-chunk

#define GST      2                      // gemm pipeline stages (BK=32)
#define GSM_PER  (128 * 36)             // floats per operand-stage ([m][32+4])
#define GSM_BYTES (GST * GSM_PER * 2 * 4)   // 73728 B dynamic smem

// ---------------- scratch (device globals; no allocs allowed) ----------------
__device__ float g_xn[TOK * DM];
__device__ float g_xz[TOK * 2 * DI];
__device__ float g_xconv[TOK * DI];
__device__ float g_dt[TOK * DI];
__device__ float g_BC[TOK * 2 * DS];
__device__ float g_BCp[KCH][TOK * 2 * DS];   // split-K partials (8MB)
__device__ float g_y[TOK * DI];
__device__ float g_A[DI * DS];
__device__ float g_Win[2 * DI * DM];         // pre-rounded weights (tf32-rna)
__device__ float g_Wdt[DI * DI];
__device__ float g_Wout[DM * DI];

// ---------------- helpers ----------------
__inline__ __device__ float warpsum(float v) {
    #pragma unroll
    for (int m = 16; m; m >>= 1) v += __shfl_xor_sync(0xffffffffu, v, m);
    return v;
}

#define RND_TF32(f) (__float_as_uint(f) + 0x1000u)   // round-to-nearest; mma ignores low 13 bits
#define RNDF(f) __uint_as_float(RND_TF32(f))

__device__ __forceinline__ void mma_tf32(float* c, const uint32_t* a, const uint32_t* b) {
    asm volatile(
        "mma.sync.aligned.m16n8k8.row.col.f32.tf32.tf32.f32 "
        "{%0,%1,%2,%3}, {%4,%5,%6,%7}, {%8,%9}, {%0,%1,%2,%3};"
        : "+f"(c[0]), "+f"(c[1]), "+f"(c[2]), "+f"(c[3])
        : "r"(a[0]), "r"(a[1]), "r"(a[2]), "r"(a[3]), "r"(b[0]), "r"(b[1]));
}

// ---------------- tf32 round-copy of ALL weights in one launch ----------------
__global__ void rnd_all(const float* __restrict__ w_in, const float* __restrict__ w_dt,
                        const float* __restrict__ w_out) {
    const int n0 = 2 * DI * DM / 4;
    const int n1 = DI * DI / 4;
    const int n2 = DM * DI / 4;
    int i = blockIdx.x * blockDim.x + threadIdx.x;
    const float4* src; uint4* dst; int j;
    if (i < n0)               { src = (const float4*)w_in;  dst = (uint4*)g_Win;  j = i; }
    else if (i < n0 + n1)     { src = (const float4*)w_dt;  dst = (uint4*)g_Wdt;  j = i - n0; }
    else if (i < n0 + n1 + n2){ src = (const float4*)w_out; dst = (uint4*)g_Wout; j = i - n0 - n1; }
    else return;
    float4 f = src[j];
    dst[j] = make_uint4(RND_TF32(f.x), RND_TF32(f.y), RND_TF32(f.z), RND_TF32(f.w));
}

// ======================================================================
//  mma.sync TF32 GEMM: C = A[M,K] @ B[N,K]^T  (A,B pre-rounded to tf32)
//  CTA 128x128, BK=32 (half the barrier periods), 8 warps 2x4,
//  warp tile 64x32, 2-stage cp.async pipeline.
//  SMEM [m][36]: cp.async.128 stores, conflict-free frag LDS.
//  EPI: 0 none, 1 softplus(v+aux[col]), 2 v+aux[idx]
// ======================================================================
template<int EPI>
__global__ void __launch_bounds__(256, 2)
gemm_mma_kernel(const float* __restrict__ A, const float* __restrict__ Bw,
                float* __restrict__ C, int M, int N, int K,
                const float* __restrict__ aux)
{
    extern __shared__ __align__(16) float sm[];
    float* Asm = sm;                       // [GST][128][36]
    float* Bsm = sm + GST * GSM_PER;

    const int tid  = threadIdx.x;
    const int lane = tid & 31;
    const int warp = tid >> 5;
    const int g    = lane >> 2;
    const int tig  = lane & 3;
    const int wm   = warp >> 2;          // 0..1
    const int wn   = warp & 3;           // 0..3
    const int bm0  = blockIdx.y * 128;
    const int bn0  = blockIdx.x * 128;

    float acc[4][4][4];
    #pragma unroll
    for (int i = 0; i < 4; i++)
        #pragma unroll
        for (int j = 0; j < 4; j++)
            #pragma unroll
            for (int q = 0; q < 4; q++) acc[i][j][q] = 0.f;

    const int r0 = tid >> 3;   // 0..31 (+32e)
    const int kq = tid & 7;    // k-octet: float4 col 4*kq

    const uint32_t aSm = (uint32_t)__cvta_generic_to_shared(Asm)
                       + (uint32_t)(r0 * 144 + kq * 16);
    const uint32_t bSm = (uint32_t)__cvta_generic_to_shared(Bsm)
                       + (uint32_t)(r0 * 144 + kq * 16);
    const uint32_t STB = GSM_PER * 4;    // 18432 B per stage

#define CPA_T(stg, k0) do { \
    const uint32_t bo = (uint32_t)(stg) * STB; \
    _Pragma("unroll") \
    for (int e = 0; e < 4; e++) { \
        asm volatile("cp.async.ca.shared.global [%0], [%1], 16;" :: \
            "r"(aSm + bo + (uint32_t)(e * 4608)), \
            "l"(A + (size_t)(bm0 + r0 + 32*e) * K + (k0) + 4*kq)); \
        asm volatile("cp.async.ca.shared.global [%0], [%1], 16;" :: \
            "r"(bSm + bo + (uint32_t)(e * 4608)), \
            "l"(Bw + (size_t)(bn0 + r0 + 32*e) * K + (k0) + 4*kq)); \
    } \
    asm volatile("cp.async.commit_group;"); \
} while (0)

    const int n_iter = K >> 5;
    CPA_T(0, 0);
    asm volatile("cp.async.wait_group 0;");
    __syncthreads();

    for (int it = 0; it < n_iter; it++) {
        const int cur = it & 1;
        if (it + 1 < n_iter) CPA_T((it + 1) & 1, (it + 1) << 5);

        const float* Ab = Asm + cur * GSM_PER;
        const float* Bb = Bsm + cur * GSM_PER;
        #pragma unroll
        for (int ks = 0; ks < 4; ks++) {
            uint32_t af[4][4], bf[4][2];
            const int k0 = ks * 8 + tig;
            const int k1 = k0 + 4;
            #pragma unroll
            for (int i = 0; i < 4; i++) {
                const int row = wm * 64 + i * 16 + g;
                af[i][0] = __float_as_uint(Ab[row * 36 + k0]);
                af[i][1] = __float_as_uint(Ab[(row + 8) * 36 + k0]);
                af[i][2] = __float_as_uint(Ab[row * 36 + k1]);
                af[i][3] = __float_as_uint(Ab[(row + 8) * 36 + k1]);
            }
            #pragma unroll
            for (int j = 0; j < 4; j++) {
                const int col = wn * 32 + j * 8 + g;
                bf[j][0] = __float_as_uint(Bb[col * 36 + k0]);
                bf[j][1] = __float_as_uint(Bb[col * 36 + k1]);
            }
            #pragma unroll
            for (int i = 0; i < 4; i++)
                #pragma unroll
                for (int j = 0; j < 4; j++)
                    mma_tf32(acc[i][j], af[i], bf[j]);
        }
        if (it + 1 < n_iter) asm volatile("cp.async.wait_group 0;");
        __syncthreads();
    }

    // ---- epilogue: direct STG (float2 pairs) ----
    #pragma unroll
    for (int i = 0; i < 4; i++) {
        const int row = bm0 + wm * 64 + i * 16 + g;
        #pragma unroll
        for (int j = 0; j < 4; j++) {
            const int col = bn0 + wn * 32 + j * 8 + 2 * tig;
            #pragma unroll
            for (int half = 0; half < 2; half++) {
                const int r = row + half * 8;
                float v0 = acc[i][j][half * 2 + 0];
                float v1 = acc[i][j][half * 2 + 1];
                size_t idx = (size_t)r * N + col;
                if (EPI == 1) {
                    v0 += aux[col];
                    v1 += aux[col + 1];
                    v0 = (v0 > 20.f) ? v0 : log1pf(__expf(v0));
                    v1 = (v1 > 20.f) ? v1 : log1pf(__expf(v1));
                } else if (EPI == 2) {
                    v0 += aux[idx];
                    v1 += aux[idx + 1];
                }
                *(float2*)(C + idx) = make_float2(v0, v1);
            }
        }
    }
#undef CPA_T
}

// ---------------- layernorm (writes tf32-rounded output) ----------------
__global__ void ln_kernel(const float* __restrict__ x, const float* __restrict__ w,
                          const float* __restrict__ b, float* __restrict__ out) {
    int t = blockIdx.x;
    int tid = threadIdx.x;
    const float* xr = x + (size_t)t * DM;
    float s = 0.f, sq = 0.f;
    for (int i = tid; i < DM; i += 256) { float v = xr[i]; s += v; sq += v * v; }
    s = warpsum(s); sq = warpsum(sq);
    __shared__ float sh0[8], sh1[8];
    int wi = tid >> 5, l = tid & 31;
    if (l == 0) { sh0[wi] = s; sh1[wi] = sq; }
    __syncthreads();
    if (wi == 0) {
        s  = (l < 8) ? sh0[l] : 0.f;
        sq = (l < 8) ? sh1[l] : 0.f;
        s = warpsum(s); sq = warpsum(sq);
        if (l == 0) { sh0[0] = s; sh1[0] = sq; }
    }
    __syncthreads();
    float mu  = sh0[0] * (1.f / DM);
    float var = sh1[0] * (1.f / DM) - mu * mu;
    float r = rsqrtf(var + 1e-5f);
    for (int i = tid; i < DM; i += 256)
        out[(size_t)t * DM + i] = RNDF((xr[i] - mu) * r * w[i] + b[i]);
}

// ---------------- A = -exp(A_log) ----------------
__global__ void prep_A(const float* __restrict__ Al, float* __restrict__ A) {
    int i = blockIdx.x * blockDim.x + threadIdx.x;
    if (i < DI * DS) A[i] = -expf(Al[i]);
}

// ---------------- BC split-K partial: 32x32 tile over K-chunk of 128 ----------------
__global__ void __launch_bounds__(256) bc_partial_kernel(
    const float* __restrict__ A, const float* __restrict__ Bp, const float* __restrict__ Bp2)
{
    constexpr int BM = 32, BN = 32, BK = 16, TM = 2, TN = 2;
    constexpr int PAD = 4;
    __shared__ float As[BK][BM + PAD];
    __shared__ float Bs[BK][BN + PAD];
    int tid = threadIdx.x;
    int kc  = blockIdx.x;                // 0..15
    int bm0 = blockIdx.y * BM;
    int kbeg = kc * KCW;
    constexpr int TX = BN / TN;
    int tx = tid % TX;
    int ty = tid / TX;

    float acc[TM][TN] = {};
    constexpr int AF4 = BM * BK / 4;
    constexpr int BF4 = BN * BK / 4;
    constexpr int KQ  = BK / 4;

    for (int k0 = kbeg; k0 < kbeg + KCW; k0 += BK) {
        #pragma unroll
        for (int q = tid; q < AF4; q += 256) {
            int row = q / KQ, c = q % KQ;
            float4 f = *(const float4*)(A + (size_t)(bm0 + row) * DI + k0 + 4 * c);
            As[4*c+0][row] = f.x; As[4*c+1][row] = f.y;
            As[4*c+2][row] = f.z; As[4*c+3][row] = f.w;
        }
        #pragma unroll
        for (int q = tid; q < BF4; q += 256) {
            int row = q / KQ, c = q % KQ;
            const float* src = (row < 16) ? (Bp + (size_t)row * DI) : (Bp2 + (size_t)(row - 16) * DI);
            float4 f = *(const float4*)(src + k0 + 4 * c);
            Bs[4*c+0][row] = f.x; Bs[4*c+1][row] = f.y;
            Bs[4*c+2][row] = f.z; Bs[4*c+3][row] = f.w;
        }
        __syncthreads();
        #pragma unroll
        for (int k = 0; k < BK; k++) {
            float a[TM], b[TN];
            #pragma unroll
            for (int i = 0; i < TM; i++) a[i] = As[k][ty * TM + i];
            #pragma unroll
            for (int j = 0; j < TN; j++) b[j] = Bs[k][tx * TN + j];
            #pragma unroll
            for (int i = 0; i < TM; i++)
                #pragma unroll
                for (int j = 0; j < TN; j++)
                    acc[i][j] = fmaf(a[i], b[j], acc[i][j]);
        }
        __syncthreads();
    }
    #pragma unroll
    for (int i = 0; i < TM; i++)
        #pragma unroll
        for (int j = 0; j < TN; j++)
            g_BCp[kc][(size_t)(bm0 + ty * TM + i) * 32 + tx * TN + j] = acc[i][j];
}

__global__ void bc_reduce_kernel() {
    int idx = blockIdx.x * blockDim.x + threadIdx.x;
    if (idx >= TOK * 32) return;
    float s = 0.f;
    #pragma unroll
    for (int kc = 0; kc < KCH; kc++) s += g_BCp[kc][idx];
    g_BC[idx] = s;
}

// ---------------- causal depthwise conv (K=4) + SiLU (tf32-rounded out) ----------------
__global__ void conv_silu_kernel(const float* __restrict__ cw, const float* __restrict__ cb) {
    int idx = blockIdx.x * blockDim.x + threadIdx.x;
    if (idx >= TOK * DI) return;
    int token = idx / DI;
    int c = idx - token * DI;
    int b = token / L_;
    int t = token - b * L_;
    float sum = cb[c];
    #pragma unroll
    for (int k = 0; k < 4; k++) {
        int tt = t - 3 + k;
        if (tt >= 0)
            sum = fmaf(g_xz[((size_t)(b * L_ + tt)) * (2 * DI) + c], cw[c * 4 + k], sum);
    }
    float s = sum / (1.f + __expf(-sum));
    g_xconv[idx] = RNDF(s);
}

// ======================================================================
//  selective scan v2 (R12 winner): 8 lanes/channel, 2 states/lane,
//  3-shfl reduce; writes tf32-rounded y for the out-GEMM.
// ======================================================================
__global__ void __launch_bounds__(256) scan_kernel(const float* __restrict__ Dv) {
    __shared__ float s_dt[2][CH][32];
    __shared__ float s_xc[2][CH][32];
    __shared__ float s_z [2][CH][32];
    __shared__ float s_bc[2][CH][32];
    __shared__ float s_y [CH][32];

    const int tid  = threadIdx.x;
    const int warp = tid >> 5;           // 0..7
    const int lane = tid & 31;
    const int b    = blockIdx.x >> 6;    // 64 d-blocks per batch
    const int dblk = (blockIdx.x & 63) * 32;
    const int sub  = lane & 7;           // state base index
    const int dgrp = lane >> 3;          // 0..3
    const int dl   = 4 * warp + dgrp;    // local channel 0..31
    const int d    = dblk + dl;

    const float a0 = g_A[d * DS + sub];
    const float a1 = g_A[d * DS + sub + 8];
    const float Dd = Dv[d];
    const size_t tok0 = (size_t)b * L_;

    float r_dt[4], r_xc[4], r_z[4], r_bc[4];

#define SCAN_LDG(t0) do { \
    _Pragma("unroll") \
    for (int e = 0; e < 4; e++) { \
        size_t tok = tok0 + (t0) + warp + 8 * e; \
        r_dt[e] = g_dt   [tok * DI + dblk + lane]; \
        r_xc[e] = g_xconv[tok * DI + dblk + lane]; \
        r_z [e] = g_xz   [tok * 2 * DI + DI + dblk + lane]; \
        r_bc[e] = g_BC   [tok * 32 + lane]; \
    } } while (0)

#define SCAN_STS(buf) do { \
    _Pragma("unroll") \
    for (int e = 0; e < 4; e++) { \
        int i = warp + 8 * e; \
        s_dt[buf][i][lane] = r_dt[e]; \
        s_xc[buf][i][lane] = r_xc[e]; \
        s_z [buf][i][lane] = r_z [e]; \
        s_bc[buf][i][lane] = r_bc[e]; \
    } } while (0)

    SCAN_LDG(0);
    SCAN_STS(0);
    __syncthreads();

    float h0 = 0.f, h1 = 0.f;
    const int n_chunks = L_ / CH;     // 64

    for (int c = 0; c < n_chunks; c++) {
        if (c + 1 < n_chunks) SCAN_LDG((c + 1) * CH);
        const int cur = c & 1;

        #pragma unroll
        for (int i = 0; i < CH; i++) {
            float dtv = s_dt[cur][i][dl];
            float xcv = s_xc[cur][i][dl];
            float B0  = s_bc[cur][i][sub];
            float B8  = s_bc[cur][i][sub + 8];
            float C0  = s_bc[cur][i][16 + sub];
            float C8  = s_bc[cur][i][24 + sub];
            float e0 = __expf(a0 * dtv);
            float e1 = __expf(a1 * dtv);
            float w  = xcv * dtv;
            h0 = fmaf(h0, e0, w * B0);
            h1 = fmaf(h1, e1, w * B8);
            float p = fmaf(h1, C8, h0 * C0);
            p += __shfl_xor_sync(0xffffffffu, p, 1);
            p += __shfl_xor_sync(0xffffffffu, p, 2);
            p += __shfl_xor_sync(0xffffffffu, p, 4);
            if (sub == 0) {
                float zv = s_z[cur][i][dl];
                float sig = zv / (1.f + __expf(-zv));
                s_y[i][dl] = (p + xcv * Dd) * sig;
            }
        }
        __syncthreads();   // scan reads + s_y writes done

        #pragma unroll
        for (int e = 0; e < 4; e++) {
            int i = warp + 8 * e;
            g_y[(tok0 + c * CH + i) * DI + dblk + lane] = RNDF(s_y[i][lane]);
        }
        if (c + 1 < n_chunks) SCAN_STS((c + 1) & 1);
        __syncthreads();   // next buffer ready; s_y drained
    }
#undef SCAN_LDG
#undef SCAN_STS
}

// ---------------- launch ----------------
extern "C" void kernel_launch(void* const* d_in, const int* in_sizes, int n_in,
                              void* d_out, int out_size) {
    const float* x      = (const float*)d_in[0];
    const float* norm_w = (const float*)d_in[1];
    const float* norm_b = (const float*)d_in[2];
    const float* W_in   = (const float*)d_in[3];
    const float* conv_w = (const float*)d_in[4];
    const float* conv_b = (const float*)d_in[5];
    const float* W_dt   = (const float*)d_in[6];
    const float* b_dt   = (const float*)d_in[7];
    const float* W_B    = (const float*)d_in[8];
    const float* W_C    = (const float*)d_in[9];
    const float* Dv     = (const float*)d_in[10];
    const float* A_log  = (const float*)d_in[11];
    const float* W_out  = (const float*)d_in[12];
    float* out = (float*)d_out;

    float *p_xn, *p_xz, *p_xc, *p_dt, *p_y, *p_A, *p_Win, *p_Wdt, *p_Wout;
    cudaGetSymbolAddress((void**)&p_xn, g_xn);
    cudaGetSymbolAddress((void**)&p_xz, g_xz);
    cudaGetSymbolAddress((void**)&p_xc, g_xconv);
    cudaGetSymbolAddress((void**)&p_dt, g_dt);
    cudaGetSymbolAddress((void**)&p_y,  g_y);
    cudaGetSymbolAddress((void**)&p_A,  g_A);
    cudaGetSymbolAddress((void**)&p_Win,  g_Win);
    cudaGetSymbolAddress((void**)&p_Wdt,  g_Wdt);
    cudaGetSymbolAddress((void**)&p_Wout, g_Wout);

    cudaFuncSetAttribute(gemm_mma_kernel<0>, cudaFuncAttributeMaxDynamicSharedMemorySize, GSM_BYTES);
    cudaFuncSetAttribute(gemm_mma_kernel<1>, cudaFuncAttributeMaxDynamicSharedMemorySize, GSM_BYTES);
    cudaFuncSetAttribute(gemm_mma_kernel<2>, cudaFuncAttributeMaxDynamicSharedMemorySize, GSM_BYTES);

    // 0. weights -> tf32-rounded copies (single launch)
    {
        int n4 = (2 * DI * DM + DI * DI + DM * DI) / 4;
        rnd_all<<<(n4 + 255) / 256, 256>>>(W_in, W_dt, W_out);
    }

    // 1. layernorm (rounded out)
    ln_kernel<<<TOK, 256>>>(x, norm_w, norm_b, p_xn);

    // 2. A = -exp(A_log)  (keeps in-proj GEMM at launch idx 3 for ncu)
    prep_A<<<(DI * DS + 255) / 256, 256>>>(A_log, p_A);

    // 3. in-proj: xz = xn @ W_in^T    [4096 x 4096 x 1024]
    {
        dim3 grid((2 * DI) / 128, TOK / 128);
        gemm_mma_kernel<0><<<grid, 256, GSM_BYTES>>>(p_xn, p_Win, p_xz, TOK, 2 * DI, DM, nullptr);
    }

    // 4. conv + silu (rounded out)
    conv_silu_kernel<<<(TOK * DI) / 256, 256>>>(conv_w, conv_b);

    // 5. dt = softplus(x_conv @ W_dt^T + b_dt)   [4096 x 2048 x 2048]
    {
        dim3 grid(DI / 128, TOK / 128);
        gemm_mma_kernel<1><<<grid, 256, GSM_BYTES>>>(p_xc, p_Wdt, p_dt, TOK, DI, DI, b_dt);
    }

    // 6. [B|C] split-K partials + reduce
    {
        dim3 grid(KCH, TOK / 32);
        bc_partial_kernel<<<grid, 256>>>(p_xc, W_B, W_C);
        bc_reduce_kernel<<<(TOK * 32 + 255) / 256, 256>>>();
    }

    // 7. selective scan + gating (rounded y out)
    scan_kernel<<<B_ * (DI / 32), 256>>>(Dv);

    // 8. out = residual + y @ W_out^T   [4096 x 1024 x 2048]
    {
        dim3 grid(DM / 128, TOK / 128);
        gemm_mma_kernel<2><<<grid, 256, GSM_BYTES>>>(p_y, p_Wout, out, TOK, DM, DI, x);
    }
}

// round 17
// speedup vs baseline: 1.1901x; 1.0266x over previous
#include <cuda_runtime.h>
#include <math.h>
#include <stdint.h>

#define B_   2
#define L_   2048
#define DM   1024
#define DI   2048
#define DS   16
#define TOK  (B_*L_)
#define CH   32            // scan time-chunk
#define NDT  2176          // dt-GEMM padded N: 2048 dt | 32 BC | 96 zero

#define GST      2                      // gemm pipeline stages (BK=32)
#define GSM_PER  (128 * 36)             // floats per operand-stage ([m][32+4])
#define GSM_BYTES (GST * GSM_PER * 2 * 4)   // 73728 B dynamic smem

// ---------------- scratch (device globals; no allocs allowed) ----------------
__device__ float g_xn[TOK * DM];
__device__ float g_xz[TOK * 2 * DI];
__device__ float g_xconv[TOK * DI];
__device__ float g_dt[TOK * DI];
__device__ float g_BC[TOK * 2 * DS];
__device__ float g_y[TOK * DI];
__device__ float g_A[DI * DS];
__device__ float g_Win[2 * DI * DM];         // pre-rounded weights (tf32-rna)
__device__ float g_Wdt[NDT * DI];            // rows: W_dt | W_B | W_C | zeros
__device__ float g_Wout[DM * DI];

// ---------------- helpers ----------------
__inline__ __device__ float warpsum(float v) {
    #pragma unroll
    for (int m = 16; m; m >>= 1) v += __shfl_xor_sync(0xffffffffu, v, m);
    return v;
}

#define RND_TF32(f) (__float_as_uint(f) + 0x1000u)   // round-to-nearest; mma ignores low 13 bits
#define RNDF(f) __uint_as_float(RND_TF32(f))

__device__ __forceinline__ void mma_tf32(float* c, const uint32_t* a, const uint32_t* b) {
    asm volatile(
        "mma.sync.aligned.m16n8k8.row.col.f32.tf32.tf32.f32 "
        "{%0,%1,%2,%3}, {%4,%5,%6,%7}, {%8,%9}, {%0,%1,%2,%3};"
        : "+f"(c[0]), "+f"(c[1]), "+f"(c[2]), "+f"(c[3])
        : "r"(a[0]), "r"(a[1]), "r"(a[2]), "r"(a[3]), "r"(b[0]), "r"(b[1]));
}

// ---------------- tf32 round-copy of ALL weights in one launch ----------------
// Also assembles the padded dt|BC weight matrix.
__global__ void rnd_all(const float* __restrict__ w_in, const float* __restrict__ w_dt,
                        const float* __restrict__ w_out,
                        const float* __restrict__ w_B, const float* __restrict__ w_C) {
    const int n0 = 2 * DI * DM / 4;      // g_Win
    const int n1 = DI * DI / 4;          // g_Wdt rows 0..2047
    const int n2 = DM * DI / 4;          // g_Wout
    const int n3 = 2 * DS * DI / 4;      // g_Wdt rows 2048..2079 (B|C)
    const int n4 = (NDT - DI - 2 * DS) * DI / 4;   // zero rows 2080..2175
    int i = blockIdx.x * blockDim.x + threadIdx.x;
    if (i < n0) {
        float4 f = ((const float4*)w_in)[i];
        ((uint4*)g_Win)[i] = make_uint4(RND_TF32(f.x), RND_TF32(f.y), RND_TF32(f.z), RND_TF32(f.w));
    } else if (i < n0 + n1) {
        int j = i - n0;
        float4 f = ((const float4*)w_dt)[j];
        ((uint4*)g_Wdt)[j] = make_uint4(RND_TF32(f.x), RND_TF32(f.y), RND_TF32(f.z), RND_TF32(f.w));
    } else if (i < n0 + n1 + n2) {
        int j = i - n0 - n1;
        float4 f = ((const float4*)w_out)[j];
        ((uint4*)g_Wout)[j] = make_uint4(RND_TF32(f.x), RND_TF32(f.y), RND_TF32(f.z), RND_TF32(f.w));
    } else if (i < n0 + n1 + n2 + n3) {
        int j = i - n0 - n1 - n2;              // float4 index within 32xDI block
        int row = j / (DI / 4);                // 0..31
        int c4  = j - row * (DI / 4);
        const float* src = (row < DS) ? (w_B + (size_t)row * DI)
                                      : (w_C + (size_t)(row - DS) * DI);
        float4 f = ((const float4*)src)[c4];
        ((uint4*)g_Wdt)[(size_t)(DI + row) * (DI / 4) + c4] =
            make_uint4(RND_TF32(f.x), RND_TF32(f.y), RND_TF32(f.z), RND_TF32(f.w));
    } else if (i < n0 + n1 + n2 + n3 + n4) {
        int j = i - n0 - n1 - n2 - n3;
        ((uint4*)g_Wdt)[(size_t)(DI + 2 * DS) * (DI / 4) + j] = make_uint4(0, 0, 0, 0);
    }
}

// ======================================================================
//  mma.sync TF32 GEMM: C = A[M,K] @ B[N,K]^T  (A,B pre-rounded to tf32)
//  CTA 128x128, BK=32, 8 warps 2x4, warp tile 64x32, 2-stage cp.async.
//  EPI: 0 none, 1 fused dt|BC (softplus cols<DI -> g_dt; cols DI..DI+31
//       -> g_BC raw; others dropped), 2 v+aux[idx] residual
// ======================================================================
template<int EPI>
__global__ void __launch_bounds__(256, 2)
gemm_mma_kernel(const float* __restrict__ A, const float* __restrict__ Bw,
                float* __restrict__ C, int M, int N, int K,
                const float* __restrict__ aux)
{
    extern __shared__ __align__(16) float sm[];
    float* Asm = sm;                       // [GST][128][36]
    float* Bsm = sm + GST * GSM_PER;

    const int tid  = threadIdx.x;
    const int lane = tid & 31;
    const int warp = tid >> 5;
    const int g    = lane >> 2;
    const int tig  = lane & 3;
    const int wm   = warp >> 2;          // 0..1
    const int wn   = warp & 3;           // 0..3
    const int bm0  = blockIdx.y * 128;
    const int bn0  = blockIdx.x * 128;

    float acc[4][4][4];
    #pragma unroll
    for (int i = 0; i < 4; i++)
        #pragma unroll
        for (int j = 0; j < 4; j++)
            #pragma unroll
            for (int q = 0; q < 4; q++) acc[i][j][q] = 0.f;

    const int r0 = tid >> 3;   // 0..31 (+32e)
    const int kq = tid & 7;    // k-octet: float4 col 4*kq

    const uint32_t aSm = (uint32_t)__cvta_generic_to_shared(Asm)
                       + (uint32_t)(r0 * 144 + kq * 16);
    const uint32_t bSm = (uint32_t)__cvta_generic_to_shared(Bsm)
                       + (uint32_t)(r0 * 144 + kq * 16);
    const uint32_t STB = GSM_PER * 4;    // 18432 B per stage

#define CPA_T(stg, k0) do { \
    const uint32_t bo = (uint32_t)(stg) * STB; \
    _Pragma("unroll") \
    for (int e = 0; e < 4; e++) { \
        asm volatile("cp.async.ca.shared.global [%0], [%1], 16;" :: \
            "r"(aSm + bo + (uint32_t)(e * 4608)), \
            "l"(A + (size_t)(bm0 + r0 + 32*e) * K + (k0) + 4*kq)); \
        asm volatile("cp.async.ca.shared.global [%0], [%1], 16;" :: \
            "r"(bSm + bo + (uint32_t)(e * 4608)), \
            "l"(Bw + (size_t)(bn0 + r0 + 32*e) * K + (k0) + 4*kq)); \
    } \
    asm volatile("cp.async.commit_group;"); \
} while (0)

    const int n_iter = K >> 5;
    CPA_T(0, 0);
    asm volatile("cp.async.wait_group 0;");
    __syncthreads();

    for (int it = 0; it < n_iter; it++) {
        const int cur = it & 1;
        if (it + 1 < n_iter) CPA_T((it + 1) & 1, (it + 1) << 5);

        const float* Ab = Asm + cur * GSM_PER;
        const float* Bb = Bsm + cur * GSM_PER;
        #pragma unroll
        for (int ks = 0; ks < 4; ks++) {
            uint32_t af[4][4], bf[4][2];
            const int k0 = ks * 8 + tig;
            const int k1 = k0 + 4;
            #pragma unroll
            for (int i = 0; i < 4; i++) {
                const int row = wm * 64 + i * 16 + g;
                af[i][0] = __float_as_uint(Ab[row * 36 + k0]);
                af[i][1] = __float_as_uint(Ab[(row + 8) * 36 + k0]);
                af[i][2] = __float_as_uint(Ab[row * 36 + k1]);
                af[i][3] = __float_as_uint(Ab[(row + 8) * 36 + k1]);
            }
            #pragma unroll
            for (int j = 0; j < 4; j++) {
                const int col = wn * 32 + j * 8 + g;
                bf[j][0] = __float_as_uint(Bb[col * 36 + k0]);
                bf[j][1] = __float_as_uint(Bb[col * 36 + k1]);
            }
            #pragma unroll
            for (int i = 0; i < 4; i++)
                #pragma unroll
                for (int j = 0; j < 4; j++)
                    mma_tf32(acc[i][j], af[i], bf[j]);
        }
        if (it + 1 < n_iter) asm volatile("cp.async.wait_group 0;");
        __syncthreads();
    }

    // ---- epilogue ----
    #pragma unroll
    for (int i = 0; i < 4; i++) {
        const int row = bm0 + wm * 64 + i * 16 + g;
        #pragma unroll
        for (int j = 0; j < 4; j++) {
            const int col = bn0 + wn * 32 + j * 8 + 2 * tig;
            #pragma unroll
            for (int half = 0; half < 2; half++) {
                const int r = row + half * 8;
                float v0 = acc[i][j][half * 2 + 0];
                float v1 = acc[i][j][half * 2 + 1];
                if (EPI == 1) {
                    if (col < DI) {           // dt region: softplus + bias
                        v0 += aux[col];
                        v1 += aux[col + 1];
                        v0 = (v0 > 20.f) ? v0 : log1pf(__expf(v0));
                        v1 = (v1 > 20.f) ? v1 : log1pf(__expf(v1));
                        *(float2*)(C + (size_t)r * DI + col) = make_float2(v0, v1);
                    } else if (col < DI + 2 * DS) {   // BC region
                        *(float2*)(g_BC + (size_t)r * 32 + (col - DI)) = make_float2(v0, v1);
                    }
                    // cols >= DI+32: dropped (zero weights)
                } else {
                    size_t idx = (size_t)r * N + col;
                    if (EPI == 2) { v0 += aux[idx]; v1 += aux[idx + 1]; }
                    *(float2*)(C + idx) = make_float2(v0, v1);
                }
            }
        }
    }
#undef CPA_T
}

// ---------------- layernorm (writes tf32-rounded output) ----------------
__global__ void ln_kernel(const float* __restrict__ x, const float* __restrict__ w,
                          const float* __restrict__ b, float* __restrict__ out) {
    int t = blockIdx.x;
    int tid = threadIdx.x;
    const float* xr = x + (size_t)t * DM;
    float s = 0.f, sq = 0.f;
    for (int i = tid; i < DM; i += 256) { float v = xr[i]; s += v; sq += v * v; }
    s = warpsum(s); sq = warpsum(sq);
    __shared__ float sh0[8], sh1[8];
    int wi = tid >> 5, l = tid & 31;
    if (l == 0) { sh0[wi] = s; sh1[wi] = sq; }
    __syncthreads();
    if (wi == 0) {
        s  = (l < 8) ? sh0[l] : 0.f;
        sq = (l < 8) ? sh1[l] : 0.f;
        s = warpsum(s); sq = warpsum(sq);
        if (l == 0) { sh0[0] = s; sh1[0] = sq; }
    }
    __syncthreads();
    float mu  = sh0[0] * (1.f / DM);
    float var = sh1[0] * (1.f / DM) - mu * mu;
    float r = rsqrtf(var + 1e-5f);
    for (int i = tid; i < DM; i += 256)
        out[(size_t)t * DM + i] = RNDF((xr[i] - mu) * r * w[i] + b[i]);
}

// ---------------- A = -exp(A_log) ----------------
__global__ void prep_A(const float* __restrict__ Al, float* __restrict__ A) {
    int i = blockIdx.x * blockDim.x + threadIdx.x;
    if (i < DI * DS) A[i] = -expf(Al[i]);
}

// ---------------- causal depthwise conv (K=4) + SiLU (tf32-rounded out) ----------------
__global__ void conv_silu_kernel(const float* __restrict__ cw, const float* __restrict__ cb) {
    int idx = blockIdx.x * blockDim.x + threadIdx.x;
    if (idx >= TOK * DI) return;
    int token = idx / DI;
    int c = idx - token * DI;
    int b = token / L_;
    int t = token - b * L_;
    float sum = cb[c];
    #pragma unroll
    for (int k = 0; k < 4; k++) {
        int tt = t - 3 + k;
        if (tt >= 0)
            sum = fmaf(g_xz[((size_t)(b * L_ + tt)) * (2 * DI) + c], cw[c * 4 + k], sum);
    }
    float s = sum / (1.f + __expf(-sum));
    g_xconv[idx] = RNDF(s);
}

// ======================================================================
//  selective scan v2 (R12 winner): 8 lanes/channel, 2 states/lane,
//  3-shfl reduce; writes tf32-rounded y for the out-GEMM.
// ======================================================================
__global__ void __launch_bounds__(256) scan_kernel(const float* __restrict__ Dv) {
    __shared__ float s_dt[2][CH][32];
    __shared__ float s_xc[2][CH][32];
    __shared__ float s_z [2][CH][32];
    __shared__ float s_bc[2][CH][32];
    __shared__ float s_y [CH][32];

    const int tid  = threadIdx.x;
    const int warp = tid >> 5;           // 0..7
    const int lane = tid & 31;
    const int b    = blockIdx.x >> 6;    // 64 d-blocks per batch
    const int dblk = (blockIdx.x & 63) * 32;
    const int sub  = lane & 7;           // state base index
    const int dgrp = lane >> 3;          // 0..3
    const int dl   = 4 * warp + dgrp;    // local channel 0..31
    const int d    = dblk + dl;

    const float a0 = g_A[d * DS + sub];
    const float a1 = g_A[d * DS + sub + 8];
    const float Dd = Dv[d];
    const size_t tok0 = (size_t)b * L_;

    float r_dt[4], r_xc[4], r_z[4], r_bc[4];

#define SCAN_LDG(t0) do { \
    _Pragma("unroll") \
    for (int e = 0; e < 4; e++) { \
        size_t tok = tok0 + (t0) + warp + 8 * e; \
        r_dt[e] = g_dt   [tok * DI + dblk + lane]; \
        r_xc[e] = g_xconv[tok * DI + dblk + lane]; \
        r_z [e] = g_xz   [tok * 2 * DI + DI + dblk + lane]; \
        r_bc[e] = g_BC   [tok * 32 + lane]; \
    } } while (0)

#define SCAN_STS(buf) do { \
    _Pragma("unroll") \
    for (int e = 0; e < 4; e++) { \
        int i = warp + 8 * e; \
        s_dt[buf][i][lane] = r_dt[e]; \
        s_xc[buf][i][lane] = r_xc[e]; \
        s_z [buf][i][lane] = r_z [e]; \
        s_bc[buf][i][lane] = r_bc[e]; \
    } } while (0)

    SCAN_LDG(0);
    SCAN_STS(0);
    __syncthreads();

    float h0 = 0.f, h1 = 0.f;
    const int n_chunks = L_ / CH;     // 64

    for (int c = 0; c < n_chunks; c++) {
        if (c + 1 < n_chunks) SCAN_LDG((c + 1) * CH);
        const int cur = c & 1;

        #pragma unroll
        for (int i = 0; i < CH; i++) {
            float dtv = s_dt[cur][i][dl];
            float xcv = s_xc[cur][i][dl];
            float B0  = s_bc[cur][i][sub];
            float B8  = s_bc[cur][i][sub + 8];
            float C0  = s_bc[cur][i][16 + sub];
            float C8  = s_bc[cur][i][24 + sub];
            float e0 = __expf(a0 * dtv);
            float e1 = __expf(a1 * dtv);
            float w  = xcv * dtv;
            h0 = fmaf(h0, e0, w * B0);
            h1 = fmaf(h1, e1, w * B8);
            float p = fmaf(h1, C8, h0 * C0);
            p += __shfl_xor_sync(0xffffffffu, p, 1);
            p += __shfl_xor_sync(0xffffffffu, p, 2);
            p += __shfl_xor_sync(0xffffffffu, p, 4);
            if (sub == 0) {
                float zv = s_z[cur][i][dl];
                float sig = zv / (1.f + __expf(-zv));
                s_y[i][dl] = (p + xcv * Dd) * sig;
            }
        }
        __syncthreads();   // scan reads + s_y writes done

        #pragma unroll
        for (int e = 0; e < 4; e++) {
            int i = warp + 8 * e;
            g_y[(tok0 + c * CH + i) * DI + dblk + lane] = RNDF(s_y[i][lane]);
        }
        if (c + 1 < n_chunks) SCAN_STS((c + 1) & 1);
        __syncthreads();   // next buffer ready; s_y drained
    }
#undef SCAN_LDG
#undef SCAN_STS
}

// ---------------- launch ----------------
extern "C" void kernel_launch(void* const* d_in, const int* in_sizes, int n_in,
                              void* d_out, int out_size) {
    const float* x      = (const float*)d_in[0];
    const float* norm_w = (const float*)d_in[1];
    const float* norm_b = (const float*)d_in[2];
    const float* W_in   = (const float*)d_in[3];
    const float* conv_w = (const float*)d_in[4];
    const float* conv_b = (const float*)d_in[5];
    const float* W_dt   = (const float*)d_in[6];
    const float* b_dt   = (const float*)d_in[7];
    const float* W_B    = (const float*)d_in[8];
    const float* W_C    = (const float*)d_in[9];
    const float* Dv     = (const float*)d_in[10];
    const float* A_log  = (const float*)d_in[11];
    const float* W_out  = (const float*)d_in[12];
    float* out = (float*)d_out;

    float *p_xn, *p_xz, *p_xc, *p_dt, *p_y, *p_A, *p_Win, *p_Wdt, *p_Wout;
    cudaGetSymbolAddress((void**)&p_xn, g_xn);
    cudaGetSymbolAddress((void**)&p_xz, g_xz);
    cudaGetSymbolAddress((void**)&p_xc, g_xconv);
    cudaGetSymbolAddress((void**)&p_dt, g_dt);
    cudaGetSymbolAddress((void**)&p_y,  g_y);
    cudaGetSymbolAddress((void**)&p_A,  g_A);
    cudaGetSymbolAddress((void**)&p_Win,  g_Win);
    cudaGetSymbolAddress((void**)&p_Wdt,  g_Wdt);
    cudaGetSymbolAddress((void**)&p_Wout, g_Wout);

    cudaFuncSetAttribute(gemm_mma_kernel<0>, cudaFuncAttributeMaxDynamicSharedMemorySize, GSM_BYTES);
    cudaFuncSetAttribute(gemm_mma_kernel<1>, cudaFuncAttributeMaxDynamicSharedMemorySize, GSM_BYTES);
    cudaFuncSetAttribute(gemm_mma_kernel<2>, cudaFuncAttributeMaxDynamicSharedMemorySize, GSM_BYTES);

    // 0. weights -> tf32-rounded copies + padded dt|BC matrix (single launch)
    {
        int n4 = (2 * DI * DM + DI * DI + DM * DI + 2 * DS * DI
                  + (NDT - DI - 2 * DS) * DI) / 4;
        rnd_all<<<(n4 + 255) / 256, 256>>>(W_in, W_dt, W_out, W_B, W_C);
    }

    // 1. layernorm (rounded out)
    ln_kernel<<<TOK, 256>>>(x, norm_w, norm_b, p_xn);

    // 2. A = -exp(A_log)  (keeps in-proj GEMM at launch idx 3 for ncu)
    prep_A<<<(DI * DS + 255) / 256, 256>>>(A_log, p_A);

    // 3. in-proj: xz = xn @ W_in^T    [4096 x 4096 x 1024]
    {
        dim3 grid((2 * DI) / 128, TOK / 128);
        gemm_mma_kernel<0><<<grid, 256, GSM_BYTES>>>(p_xn, p_Win, p_xz, TOK, 2 * DI, DM, nullptr);
    }

    // 4. conv + silu (rounded out)
    conv_silu_kernel<<<(TOK * DI) / 256, 256>>>(conv_w, conv_b);

    // 5. fused dt|BC GEMM: [4096 x 2176 x 2048]
    //    cols 0..2047 -> softplus -> g_dt ; cols 2048..2079 -> g_BC
    {
        dim3 grid(NDT / 128, TOK / 128);
        gemm_mma_kernel<1><<<grid, 256, GSM_BYTES>>>(p_xc, p_Wdt, p_dt, TOK, NDT, DI, b_dt);
    }

    // 6. selective scan + gating (rounded y out)
    scan_kernel<<<B_ * (DI / 32), 256>>>(Dv);

    // 7. out = residual + y @ W_out^T   [4096 x 1024 x 2048]
    {
        dim3 grid(DM / 128, TOK / 128);
        gemm_mma_kernel<2><<<grid, 256, GSM_BYTES>>>(p_y, p_Wout, out, TOK, DM, DI, x);
    }
}